// round 6
// baseline (speedup 1.0000x reference)
#include <cuda_runtime.h>
#include <cuda_bf16.h>
#include <cstdint>
#include <math.h>

// Problem dims (fixed by the dataset)
#define BSZ 16
#define QQ  300
#define NC  81
#define HH  64
#define WWD 64
#define TT  400
#define HM  128
#define PP  (BSZ*QQ)     // 4800
#define HWX (HH*WWD)     // 4096

// ---------------- scratch (device globals; no allocation allowed) -------------
__device__ __align__(16) __nv_bfloat16 g_A1[(size_t)PP*HWX];   // logits bf16
__device__ __align__(16) __nv_bfloat16 g_A2[(size_t)PP*HWX];   // sigmoid bf16
__device__ __align__(16) __nv_bfloat16 g_tm[(size_t)TT*HWX];   // resized targets bf16
__device__ float g_tsum[TT];
__device__ float g_snp[PP];     // sum log_sigmoid(-m)
__device__ float g_psum[PP];    // sum sigmoid(m)
__device__ float g_prob[(size_t)PP*NC];
__device__ int   g_lab[TT];     // decoded labels

// ---------------- small helpers -----------------------------------------------
__device__ __forceinline__ float block_reduce_sum(float v, float* sh) {
    int lane = threadIdx.x & 31, w = threadIdx.x >> 5;
#pragma unroll
    for (int o = 16; o; o >>= 1) v += __shfl_down_sync(0xffffffffu, v, o);
    if (lane == 0) sh[w] = v;
    __syncthreads();
    if (w == 0) {
        v = (lane < 8) ? sh[lane] : 0.f;
#pragma unroll
        for (int o = 4; o; o >>= 1) v += __shfl_down_sync(0xffffffffu, v, o);
    }
    return v;  // valid on thread 0
}

__device__ __forceinline__ void taps64(int i, int& j0, float w[4]) {
    if (i == 0)       { j0 = 0;   w[0] = 3.f/7.f; w[1] = 3.f/7.f; w[2] = 1.f/7.f; w[3] = 0.f; }
    else if (i == 63) { j0 = 124; w[0] = 0.f;     w[1] = 1.f/7.f; w[2] = 3.f/7.f; w[3] = 3.f/7.f; }
    else              { j0 = 2*i - 1; w[0] = 0.125f; w[1] = 0.375f; w[2] = 0.375f; w[3] = 0.125f; }
}

__device__ __forceinline__ void cpa16(void* dst, const void* src, bool v) {
    uint32_t d = (uint32_t)__cvta_generic_to_shared(dst);
    int n = v ? 16 : 0;
    asm volatile("cp.async.cg.shared.global [%0], [%1], 16, %2;\n" :: "r"(d), "l"(src), "r"(n));
}
__device__ __forceinline__ void cpcommit() { asm volatile("cp.async.commit_group;\n"); }

__device__ __forceinline__ void mma16816(float c[4], const uint32_t a[4], const uint32_t b[2]) {
    asm volatile(
        "mma.sync.aligned.m16n8k16.row.col.f32.bf16.bf16.f32 "
        "{%0,%1,%2,%3}, {%4,%5,%6,%7}, {%8,%9}, {%0,%1,%2,%3};\n"
        : "+f"(c[0]), "+f"(c[1]), "+f"(c[2]), "+f"(c[3])
        : "r"(a[0]), "r"(a[1]), "r"(a[2]), "r"(a[3]), "r"(b[0]), "r"(b[1]));
}

// ---------------- fused aux kernel (label + resize + prep + prob) -------------
__global__ void __launch_bounds__(256) aux_kernel(
    const float* __restrict__ logits, const float* __restrict__ masks,
    const float* __restrict__ tmasks, const void* __restrict__ labels) {
    __shared__ __align__(16) char smr[HM * HH * 4];   // 32KB, branch-dependent use
    int bid = blockIdx.x, tid = threadIdx.x;

    if (bid < PP) {
        // ---- prep: bf16 logits + sigmoid + row stats ----
        int p = bid;
        const float4* src = (const float4*)(masks + (size_t)p * HWX);
        __nv_bfloat162* d1 = (__nv_bfloat162*)(g_A1 + (size_t)p * HWX);
        __nv_bfloat162* d2 = (__nv_bfloat162*)(g_A2 + (size_t)p * HWX);
        float accn = 0.f, accs = 0.f;
        for (int i = tid; i < HWX / 4; i += 256) {
            float4 v = src[i];
            float m[4] = {v.x, v.y, v.z, v.w};
            float s[4];
#pragma unroll
            for (int j = 0; j < 4; ++j) {
                s[j] = 1.f / (1.f + expf(-m[j]));
                accn -= (fmaxf(m[j], 0.f) + log1pf(expf(-fabsf(m[j]))));
                accs += s[j];
            }
            __nv_bfloat162 a, b;
            a.x = __float2bfloat16(m[0]); a.y = __float2bfloat16(m[1]);
            b.x = __float2bfloat16(m[2]); b.y = __float2bfloat16(m[3]);
            d1[2*i] = a; d1[2*i + 1] = b;
            a.x = __float2bfloat16(s[0]); a.y = __float2bfloat16(s[1]);
            b.x = __float2bfloat16(s[2]); b.y = __float2bfloat16(s[3]);
            d2[2*i] = a; d2[2*i + 1] = b;
        }
        float* shred = (float*)smr;
        float tn = block_reduce_sum(accn, shred);
        __syncthreads();
        float ts = block_reduce_sum(accs, shred);
        if (tid == 0) { g_snp[p] = tn; g_psum[p] = ts; }
    } else if (bid < PP + TT) {
        // ---- resize target masks 128->64 (antialiased bilinear) + row sums ----
        int t = bid - PP;
        const float* src = tmasks + (size_t)t * HM * HM;
        float (*htmp)[HH] = (float(*)[HH])smr;
        for (int e = tid; e < HM * HH; e += 256) {
            int r = e >> 6, i = e & 63;
            int j0; float w[4]; taps64(i, j0, w);
            const float* row = src + r * HM;
            htmp[r][i] = w[0]*row[j0] + w[1]*row[j0+1] + w[2]*row[j0+2] + w[3]*row[j0+3];
        }
        __syncthreads();
        float lsum = 0.f;
        for (int e = tid; e < HWX; e += 256) {
            int o = e >> 6, i = e & 63;
            int j0; float w[4]; taps64(o, j0, w);
            float v = w[0]*htmp[j0][i] + w[1]*htmp[j0+1][i] + w[2]*htmp[j0+2][i] + w[3]*htmp[j0+3][i];
            g_tm[(size_t)t * HWX + e] = __float2bfloat16(v);
            lsum += v;
        }
        __syncthreads();
        __shared__ float shred2[8];
        float tot = block_reduce_sum(lsum, shred2);
        if (tid == 0) g_tsum[t] = tot;
    } else if (bid < PP + TT + PP) {
        // ---- softmax probs over 81 classes ----
        int p = bid - PP - TT;
        float* sh = (float*)smr;
        float x = (tid < NC) ? logits[(size_t)p * NC + tid] : -1e30f;
        if (tid < 128) sh[tid] = x;
        __syncthreads();
        for (int s = 64; s > 0; s >>= 1) { if (tid < s) sh[tid] = fmaxf(sh[tid], sh[tid + s]); __syncthreads(); }
        float mx = sh[0]; __syncthreads();
        float e = (tid < NC) ? expf(x - mx) : 0.f;
        if (tid < 128) sh[tid] = e;
        __syncthreads();
        for (int s = 64; s > 0; s >>= 1) { if (tid < s) sh[tid] += sh[tid + s]; __syncthreads(); }
        float inv = 1.f / sh[0];
        if (tid < NC) g_prob[(size_t)p * NC + tid] = e * inv;
    } else {
        // ---- label decode (robust to int32/int64) ----
        __shared__ int odd_nz;
        if (tid == 0) odd_nz = 0;
        __syncthreads();
        const int* li = (const int*)labels;
        for (int i = tid; i < TT / 2; i += 256)
            if (li[2 * i + 1] != 0) atomicOr(&odd_nz, 1);
        __syncthreads();
        bool is64 = (odd_nz == 0);
        for (int t = tid; t < TT; t += 256)
            g_lab[t] = is64 ? (int)((const long long*)labels)[t] : li[t];
    }
}

// ---------------- dual GEMM (mma.sync, 4-stage cp.async) + cost epilogue ------
#define BM 128
#define BN 128
#define BK 32
#define SAK 40            // padded K stride in bf16 elems (80B rows)
#define STAGES 4
#define KT_N (HWX / BK)   // 128 k-tiles

struct TInfo {
    float cx, cy, w, h, x0, y0, x1, y1, area, tsum;
    int lab, pad;
};

// per stage: A1 + A2 + B, each 128 rows x SAK elems
#define STAGE_ELEMS (3 * BM * SAK)
#define SMEM_BYTES (STAGES * STAGE_ELEMS * 2 + 128 * (int)sizeof(TInfo))

__global__ void __launch_bounds__(256, 1) gemm_kernel(
    const float* __restrict__ pboxes, const float* __restrict__ tboxes,
    float* __restrict__ out) {
    extern __shared__ __align__(16) char smem_raw[];
    __nv_bfloat16* sBuf = (__nv_bfloat16*)smem_raw;            // STAGES*STAGE_ELEMS
    TInfo* sT = (TInfo*)(smem_raw + STAGES * STAGE_ELEMS * 2); // 128 entries

    int tid = threadIdx.x, lane = tid & 31, warp = tid >> 5;
    int n0 = blockIdx.x * BN, m0 = blockIdx.y * BM;
    int nvalid = min(BN, TT - n0);
    int wr = (warp >> 1) * 32;   // 4 warps along M (32 rows each)
    int wc = (warp & 1) * 64;    // 2 warps along N (64 cols each)

    if (tid < 128) {
        int t = n0 + tid;
        TInfo ti;
        if (t < TT) {
            float4 tb = *(const float4*)(tboxes + 4 * t);
            ti.cx = tb.x; ti.cy = tb.y; ti.w = tb.z; ti.h = tb.w;
            ti.x0 = tb.x - 0.5f * tb.z; ti.y0 = tb.y - 0.5f * tb.w;
            ti.x1 = tb.x + 0.5f * tb.z; ti.y1 = tb.y + 0.5f * tb.w;
            ti.area = tb.z * tb.w;
            ti.tsum = g_tsum[t];
            ti.lab = g_lab[t];
        } else {
            ti.cx = ti.cy = ti.w = ti.h = 0.f;
            ti.x0 = ti.y0 = ti.x1 = ti.y1 = 0.f;
            ti.area = ti.tsum = 0.f; ti.lab = 0;
        }
        ti.pad = 0;
        sT[tid] = ti;
    }

    float acc[2][2][8][4];
#pragma unroll
    for (int a = 0; a < 2; ++a)
#pragma unroll
        for (int b = 0; b < 2; ++b)
#pragma unroll
            for (int c = 0; c < 8; ++c)
#pragma unroll
                for (int d = 0; d < 4; ++d) acc[a][b][c][d] = 0.f;

    // stage loader: 3 mats x 128 rows x 4 chunks(16B) = 1536 cp.async; 6/thread
    auto loadStage = [&](int slot, int kt) {
        __nv_bfloat16* base = sBuf + slot * STAGE_ELEMS;
        int k0 = kt * BK;
#pragma unroll
        for (int it = 0; it < 6; ++it) {
            int i = tid + it * 256;
            int mat = i >> 9;          // 0..2
            int rem = i & 511;
            int row = rem >> 2;        // 0..127
            int ch  = rem & 3;         // 0..3
            __nv_bfloat16* dst = base + mat * BM * SAK + row * SAK + ch * 8;
            const __nv_bfloat16* src;
            bool v;
            if (mat < 2) {
                int p = m0 + row;
                v = p < PP;
                const __nv_bfloat16* g = (mat == 0) ? g_A1 : g_A2;
                src = g + ((size_t)(v ? p : 0) * HWX + k0 + ch * 8);
            } else {
                int t = n0 + row;
                v = t < TT;
                src = g_tm + ((size_t)(v ? t : 0) * HWX + k0 + ch * 8);
            }
            cpa16(dst, src, v);
        }
        cpcommit();
    };

    // prologue: fill stages 0..2
    loadStage(0, 0);
    loadStage(1, 1);
    loadStage(2, 2);

    for (int kt = 0; kt < KT_N; ++kt) {
        asm volatile("cp.async.wait_group 2;" ::: "memory");
        __syncthreads();

        const __nv_bfloat16* S = sBuf + (kt & 3) * STAGE_ELEMS;
        const __nv_bfloat16* A1s = S;
        const __nv_bfloat16* A2s = S + BM * SAK;
        const __nv_bfloat16* Bs  = S + 2 * BM * SAK;
#pragma unroll
        for (int ks = 0; ks < 2; ++ks) {
            int cb = ks * 16 + 2 * (lane & 3);
            uint32_t af[2][2][4];
#pragma unroll
            for (int mi = 0; mi < 2; ++mi) {
                int r = wr + mi * 16 + (lane >> 2);
                af[0][mi][0] = *(const uint32_t*)(A1s + r * SAK + cb);
                af[0][mi][1] = *(const uint32_t*)(A1s + (r + 8) * SAK + cb);
                af[0][mi][2] = *(const uint32_t*)(A1s + r * SAK + cb + 8);
                af[0][mi][3] = *(const uint32_t*)(A1s + (r + 8) * SAK + cb + 8);
                af[1][mi][0] = *(const uint32_t*)(A2s + r * SAK + cb);
                af[1][mi][1] = *(const uint32_t*)(A2s + (r + 8) * SAK + cb);
                af[1][mi][2] = *(const uint32_t*)(A2s + r * SAK + cb + 8);
                af[1][mi][3] = *(const uint32_t*)(A2s + (r + 8) * SAK + cb + 8);
            }
            uint32_t bf[8][2];
#pragma unroll
            for (int ni = 0; ni < 8; ++ni) {
                int n = wc + ni * 8 + (lane >> 2);
                bf[ni][0] = *(const uint32_t*)(Bs + n * SAK + cb);
                bf[ni][1] = *(const uint32_t*)(Bs + n * SAK + cb + 8);
            }
#pragma unroll
            for (int s2 = 0; s2 < 2; ++s2)
#pragma unroll
                for (int mi = 0; mi < 2; ++mi)
#pragma unroll
                    for (int ni = 0; ni < 8; ++ni)
                        mma16816(acc[s2][mi][ni], af[s2][mi], bf[ni]);
        }
        __syncthreads();
        int kl = kt + STAGES - 1;
        if (kl < KT_N) loadStage(kl & 3, kl);
    }

    // ---- fused cost epilogue ----
    const float inv_hw = 1.0f / (float)HWX;
#pragma unroll
    for (int mi = 0; mi < 2; ++mi) {
#pragma unroll
        for (int rh = 0; rh < 2; ++rh) {
            int p = m0 + wr + mi * 16 + (lane >> 2) + rh * 8;
            if (p >= PP) continue;
            float snp_p = g_snp[p], psum_p = g_psum[p];
            float4 pb = *(const float4*)(pboxes + 4 * p);
            float px0 = pb.x - 0.5f * pb.z, py0 = pb.y - 0.5f * pb.w;
            float px1 = pb.x + 0.5f * pb.z, py1 = pb.y + 0.5f * pb.w;
            float parea = pb.z * pb.w;
            const float* prow = g_prob + (size_t)p * NC;
#pragma unroll
            for (int ni = 0; ni < 8; ++ni) {
                int tl0 = wc + ni * 8 + 2 * (lane & 3);
                if (tl0 >= nvalid) continue;
                float r2[2];
#pragma unroll
                for (int cc = 0; cc < 2; ++cc) {
                    TInfo ti = sT[tl0 + cc];
                    float d1 = acc[0][mi][ni][rh * 2 + cc];
                    float d2 = acc[1][mi][ni][rh * 2 + cc];
                    float l1 = fabsf(pb.x - ti.cx) + fabsf(pb.y - ti.cy)
                             + fabsf(pb.z - ti.w) + fabsf(pb.w - ti.h);
                    float ix0 = fmaxf(px0, ti.x0), iy0 = fmaxf(py0, ti.y0);
                    float ix1 = fminf(px1, ti.x1), iy1 = fminf(py1, ti.y1);
                    float inter = fmaxf(ix1 - ix0, 0.f) * fmaxf(iy1 - iy0, 0.f);
                    float uni = parea + ti.area - inter;
                    float iou = inter / uni;
                    float ex0 = fminf(px0, ti.x0), ey0 = fminf(py0, ti.y0);
                    float ex1 = fmaxf(px1, ti.x1), ey1 = fmaxf(py1, ti.y1);
                    float enc = fmaxf(ex1 - ex0, 0.f) * fmaxf(ey1 - ey0, 0.f);
                    float giou = iou - (enc - uni) / enc;
                    float cmask = -(d1 + snp_p) * inv_hw;
                    float cdice = 1.f - (2.f * d2 + 1e-5f) / (psum_p + ti.tsum + 1e-5f);
                    float ccls = -prow[ti.lab];
                    r2[cc] = 5.f * l1 - 2.f * giou + 2.f * ccls + 5.f * cmask + 5.f * cdice;
                }
                *(float2*)(out + (size_t)p * TT + n0 + tl0) = make_float2(r2[0], r2[1]);
            }
        }
    }
}

// ---------------- launch ------------------------------------------------------
extern "C" void kernel_launch(void* const* d_in, const int* in_sizes, int n_in,
                              void* d_out, int out_size) {
    const float* pred_logits = (const float*)d_in[0];
    const float* pred_boxes  = (const float*)d_in[1];
    const float* pred_masks  = (const float*)d_in[2];
    const float* tgt_boxes   = (const float*)d_in[3];
    const float* tgt_masks   = (const float*)d_in[4];
    const void*  tgt_labels  = (const void*)d_in[5];
    float* out = (float*)d_out;

    aux_kernel<<<PP + TT + PP + 1, 256>>>(pred_logits, pred_masks, tgt_masks, tgt_labels);

    cudaFuncSetAttribute(gemm_kernel, cudaFuncAttributeMaxDynamicSharedMemorySize, SMEM_BYTES);
    gemm_kernel<<<dim3((TT + BN - 1) / BN, (PP + BM - 1) / BM), 256, SMEM_BYTES>>>(
        pred_boxes, tgt_boxes, out);
}

// round 9
// speedup vs baseline: 1.0677x; 1.0677x over previous
#include <cuda_runtime.h>
#include <cuda_bf16.h>
#include <cstdint>
#include <math.h>

// Problem dims (fixed by the dataset)
#define BSZ 16
#define QQ  300
#define NC  81
#define HH  64
#define WWD 64
#define TT  400
#define HM  128
#define PP  (BSZ*QQ)     // 4800
#define HWX (HH*WWD)     // 4096

// ---------------- scratch (device globals; no allocation allowed) -------------
__device__ __align__(16) __nv_bfloat16 g_A1[(size_t)PP*HWX];   // logits bf16
__device__ __align__(16) __nv_bfloat16 g_A2[(size_t)PP*HWX];   // sigmoid bf16
__device__ __align__(16) __nv_bfloat16 g_tm[(size_t)TT*HWX];   // resized targets bf16
__device__ float g_tsum[TT];
__device__ float g_snp[PP];     // sum log_sigmoid(-m)
__device__ float g_psum[PP];    // sum sigmoid(m)
__device__ float g_prob[(size_t)PP*NC];
__device__ int   g_lab[TT];     // decoded labels

// ---------------- small helpers -----------------------------------------------
__device__ __forceinline__ float block_reduce_sum(float v, float* sh) {
    int lane = threadIdx.x & 31, w = threadIdx.x >> 5;
#pragma unroll
    for (int o = 16; o; o >>= 1) v += __shfl_down_sync(0xffffffffu, v, o);
    if (lane == 0) sh[w] = v;
    __syncthreads();
    if (w == 0) {
        v = (lane < 8) ? sh[lane] : 0.f;
#pragma unroll
        for (int o = 4; o; o >>= 1) v += __shfl_down_sync(0xffffffffu, v, o);
    }
    return v;  // valid on thread 0
}

__device__ __forceinline__ void taps64(int i, int& j0, float w[4]) {
    if (i == 0)       { j0 = 0;   w[0] = 3.f/7.f; w[1] = 3.f/7.f; w[2] = 1.f/7.f; w[3] = 0.f; }
    else if (i == 63) { j0 = 124; w[0] = 0.f;     w[1] = 1.f/7.f; w[2] = 3.f/7.f; w[3] = 3.f/7.f; }
    else              { j0 = 2*i - 1; w[0] = 0.125f; w[1] = 0.375f; w[2] = 0.375f; w[3] = 0.125f; }
}

__device__ __forceinline__ void cpa16(void* dst, const void* src, bool v) {
    uint32_t d = (uint32_t)__cvta_generic_to_shared(dst);
    int n = v ? 16 : 0;
    asm volatile("cp.async.cg.shared.global [%0], [%1], 16, %2;\n" :: "r"(d), "l"(src), "r"(n));
}
__device__ __forceinline__ void cpcommit() { asm volatile("cp.async.commit_group;\n"); }

__device__ __forceinline__ void mma16816(float c[4], const uint32_t a[4], const uint32_t b[2]) {
    asm volatile(
        "mma.sync.aligned.m16n8k16.row.col.f32.bf16.bf16.f32 "
        "{%0,%1,%2,%3}, {%4,%5,%6,%7}, {%8,%9}, {%0,%1,%2,%3};\n"
        : "+f"(c[0]), "+f"(c[1]), "+f"(c[2]), "+f"(c[3])
        : "r"(a[0]), "r"(a[1]), "r"(a[2]), "r"(a[3]), "r"(b[0]), "r"(b[1]));
}

__device__ __forceinline__ void ldsm_x4(uint32_t r[4], uint32_t addr) {
    asm volatile("ldmatrix.sync.aligned.m8n8.x4.shared.b16 {%0,%1,%2,%3}, [%4];"
        : "=r"(r[0]), "=r"(r[1]), "=r"(r[2]), "=r"(r[3]) : "r"(addr));
}

// ---------------- fused aux kernel (label + resize + prep + prob) -------------
__global__ void __launch_bounds__(256) aux_kernel(
    const float* __restrict__ logits, const float* __restrict__ masks,
    const float* __restrict__ tmasks, const void* __restrict__ labels) {
    __shared__ __align__(16) char smr[HM * HH * 4];   // 32KB, branch-dependent use
    int bid = blockIdx.x, tid = threadIdx.x;

    if (bid < PP) {
        // ---- prep: bf16 logits + sigmoid + row stats ----
        int p = bid;
        const float4* src = (const float4*)(masks + (size_t)p * HWX);
        __nv_bfloat162* d1 = (__nv_bfloat162*)(g_A1 + (size_t)p * HWX);
        __nv_bfloat162* d2 = (__nv_bfloat162*)(g_A2 + (size_t)p * HWX);
        float accn = 0.f, accs = 0.f;
        for (int i = tid; i < HWX / 4; i += 256) {
            float4 v = src[i];
            float m[4] = {v.x, v.y, v.z, v.w};
            float s[4];
#pragma unroll
            for (int j = 0; j < 4; ++j) {
                float e = __expf(-fabsf(m[j]));
                float l = __logf(1.f + e);
                s[j] = (m[j] >= 0.f) ? __fdividef(1.f, 1.f + e)
                                     : __fdividef(e, 1.f + e);
                accn -= (fmaxf(m[j], 0.f) + l);
                accs += s[j];
            }
            __nv_bfloat162 a, b;
            a.x = __float2bfloat16(m[0]); a.y = __float2bfloat16(m[1]);
            b.x = __float2bfloat16(m[2]); b.y = __float2bfloat16(m[3]);
            d1[2*i] = a; d1[2*i + 1] = b;
            a.x = __float2bfloat16(s[0]); a.y = __float2bfloat16(s[1]);
            b.x = __float2bfloat16(s[2]); b.y = __float2bfloat16(s[3]);
            d2[2*i] = a; d2[2*i + 1] = b;
        }
        float* shred = (float*)smr;
        float tn = block_reduce_sum(accn, shred);
        __syncthreads();
        float ts = block_reduce_sum(accs, shred);
        if (tid == 0) { g_snp[p] = tn; g_psum[p] = ts; }
    } else if (bid < PP + TT) {
        // ---- resize target masks 128->64 (antialiased bilinear) + row sums ----
        int t = bid - PP;
        const float* src = tmasks + (size_t)t * HM * HM;
        float (*htmp)[HH] = (float(*)[HH])smr;
        for (int e = tid; e < HM * HH; e += 256) {
            int r = e >> 6, i = e & 63;
            int j0; float w[4]; taps64(i, j0, w);
            const float* row = src + r * HM;
            htmp[r][i] = w[0]*row[j0] + w[1]*row[j0+1] + w[2]*row[j0+2] + w[3]*row[j0+3];
        }
        __syncthreads();
        float lsum = 0.f;
        for (int e = tid; e < HWX; e += 256) {
            int o = e >> 6, i = e & 63;
            int j0; float w[4]; taps64(o, j0, w);
            float v = w[0]*htmp[j0][i] + w[1]*htmp[j0+1][i] + w[2]*htmp[j0+2][i] + w[3]*htmp[j0+3][i];
            g_tm[(size_t)t * HWX + e] = __float2bfloat16(v);
            lsum += v;
        }
        __syncthreads();
        __shared__ float shred2[8];
        float tot = block_reduce_sum(lsum, shred2);
        if (tid == 0) g_tsum[t] = tot;
    } else if (bid < PP + TT + PP) {
        // ---- softmax probs over 81 classes ----
        int p = bid - PP - TT;
        float* sh = (float*)smr;
        float x = (tid < NC) ? logits[(size_t)p * NC + tid] : -1e30f;
        if (tid < 128) sh[tid] = x;
        __syncthreads();
        for (int s = 64; s > 0; s >>= 1) { if (tid < s) sh[tid] = fmaxf(sh[tid], sh[tid + s]); __syncthreads(); }
        float mx = sh[0]; __syncthreads();
        float e = (tid < NC) ? __expf(x - mx) : 0.f;
        if (tid < 128) sh[tid] = e;
        __syncthreads();
        for (int s = 64; s > 0; s >>= 1) { if (tid < s) sh[tid] += sh[tid + s]; __syncthreads(); }
        float inv = __fdividef(1.f, sh[0]);
        if (tid < NC) g_prob[(size_t)p * NC + tid] = e * inv;
    } else {
        // ---- label decode (robust to int32/int64) ----
        __shared__ int odd_nz;
        if (tid == 0) odd_nz = 0;
        __syncthreads();
        const int* li = (const int*)labels;
        for (int i = tid; i < TT / 2; i += 256)
            if (li[2 * i + 1] != 0) atomicOr(&odd_nz, 1);
        __syncthreads();
        bool is64 = (odd_nz == 0);
        for (int t = tid; t < TT; t += 256)
            g_lab[t] = is64 ? (int)((const long long*)labels)[t] : li[t];
    }
}

// ---------------- dual GEMM (mma.sync + ldmatrix, 4-stage) + cost epilogue ----
#define BM 128
#define BN 128
#define BK 32
#define SAK 40            // padded K stride in bf16 elems (80B rows, LDSM-conflict-free)
#define STAGES 4
#define KT_N (HWX / BK)   // 128 k-tiles
#define NTHREADS 512

struct TInfo {
    float cx, cy, w, h, x0, y0, x1, y1, area, tsum;
    int lab, pad;
};

#define STAGE_ELEMS (3 * BM * SAK)
#define SMEM_BYTES (STAGES * STAGE_ELEMS * 2 + 128 * (int)sizeof(TInfo))

__global__ void __launch_bounds__(NTHREADS, 1) gemm_kernel(
    const float* __restrict__ pboxes, const float* __restrict__ tboxes,
    float* __restrict__ out) {
    extern __shared__ __align__(16) char smem_raw[];
    __nv_bfloat16* sBuf = (__nv_bfloat16*)smem_raw;
    TInfo* sT = (TInfo*)(smem_raw + STAGES * STAGE_ELEMS * 2);

    int tid = threadIdx.x, lane = tid & 31, warp = tid >> 5;
    int n0 = blockIdx.x * BN, m0 = blockIdx.y * BM;
    int nvalid = min(BN, TT - n0);
    int wr = (warp & 3) * 32;    // 4 warps along M (32 rows each)
    int wc = (warp >> 2) * 32;   // 4 warps along N (32 cols each)

    if (tid < 128) {
        int t = n0 + tid;
        TInfo ti;
        if (t < TT) {
            float4 tb = *(const float4*)(tboxes + 4 * t);
            ti.cx = tb.x; ti.cy = tb.y; ti.w = tb.z; ti.h = tb.w;
            ti.x0 = tb.x - 0.5f * tb.z; ti.y0 = tb.y - 0.5f * tb.w;
            ti.x1 = tb.x + 0.5f * tb.z; ti.y1 = tb.y + 0.5f * tb.w;
            ti.area = tb.z * tb.w;
            ti.tsum = g_tsum[t];
            ti.lab = g_lab[t];
        } else {
            ti.cx = ti.cy = ti.w = ti.h = 0.f;
            ti.x0 = ti.y0 = ti.x1 = ti.y1 = 0.f;
            ti.area = ti.tsum = 0.f; ti.lab = 0;
        }
        ti.pad = 0;
        sT[tid] = ti;
    }

    float acc[2][2][4][4];   // [mat][mi][ni][frag]
#pragma unroll
    for (int a = 0; a < 2; ++a)
#pragma unroll
        for (int b = 0; b < 2; ++b)
#pragma unroll
            for (int c = 0; c < 4; ++c)
#pragma unroll
                for (int d = 0; d < 4; ++d) acc[a][b][c][d] = 0.f;

    // LDSM source addresses (per-lane, element offsets within a stage)
    int a_row_l = (lane & 15);
    int a_col_l = (lane >> 4) * 8;
    int b_row_l = (lane & 7) + ((lane >> 4) * 8);
    int b_col_l = ((lane >> 3) & 1) * 8;

    // stage loader: 3 mats x 128 rows x 4 chunks(16B) = 1536 cp.async; 3/thread
    auto loadStage = [&](int slot, int kt) {
        __nv_bfloat16* base = sBuf + slot * STAGE_ELEMS;
        int k0 = kt * BK;
#pragma unroll
        for (int it = 0; it < 3; ++it) {
            int i = tid + it * NTHREADS;
            int mat = i >> 9;          // 0..2
            int rem = i & 511;
            int row = rem >> 2;        // 0..127
            int ch  = rem & 3;         // 0..3
            __nv_bfloat16* dst = base + mat * BM * SAK + row * SAK + ch * 8;
            const __nv_bfloat16* src;
            bool v;
            if (mat < 2) {
                int p = m0 + row;
                v = p < PP;
                const __nv_bfloat16* g = (mat == 0) ? g_A1 : g_A2;
                src = g + ((size_t)(v ? p : 0) * HWX + k0 + ch * 8);
            } else {
                int t = n0 + row;
                v = t < TT;
                src = g_tm + ((size_t)(v ? t : 0) * HWX + k0 + ch * 8);
            }
            cpa16(dst, src, v);
        }
        cpcommit();
    };

    loadStage(0, 0);
    loadStage(1, 1);
    loadStage(2, 2);

    for (int kt = 0; kt < KT_N; ++kt) {
        asm volatile("cp.async.wait_group 2;" ::: "memory");
        __syncthreads();
        // issue next load FIRST (slot was consumed at kt-1; barrier above ordered it)
        int kl = kt + STAGES - 1;
        if (kl < KT_N) loadStage(kl & 3, kl);

        const __nv_bfloat16* S = sBuf + (kt & 3) * STAGE_ELEMS;
        uint32_t sbA1 = (uint32_t)__cvta_generic_to_shared(S);
        uint32_t sbA2 = sbA1 + BM * SAK * 2;
        uint32_t sbB  = sbA1 + 2 * BM * SAK * 2;
#pragma unroll
        for (int ks = 0; ks < 2; ++ks) {
            int cb = ks * 16;
            uint32_t af[2][2][4];
#pragma unroll
            for (int mi = 0; mi < 2; ++mi) {
                uint32_t ra = ((wr + mi * 16 + a_row_l) * SAK + cb + a_col_l) * 2;
                ldsm_x4(af[0][mi], sbA1 + ra);
                ldsm_x4(af[1][mi], sbA2 + ra);
            }
            uint32_t bf[4][2];
#pragma unroll
            for (int nh = 0; nh < 2; ++nh) {
                uint32_t regs[4];
                uint32_t rb = ((wc + nh * 16 + b_row_l) * SAK + cb + b_col_l) * 2;
                ldsm_x4(regs, sbB + rb);
                bf[nh * 2][0] = regs[0]; bf[nh * 2][1] = regs[1];
                bf[nh * 2 + 1][0] = regs[2]; bf[nh * 2 + 1][1] = regs[3];
            }
#pragma unroll
            for (int s2 = 0; s2 < 2; ++s2)
#pragma unroll
                for (int mi = 0; mi < 2; ++mi)
#pragma unroll
                    for (int ni = 0; ni < 4; ++ni)
                        mma16816(acc[s2][mi][ni], af[s2][mi], bf[ni]);
        }
    }

    // ---- fused cost epilogue ----
    const float inv_hw = 1.0f / (float)HWX;
#pragma unroll
    for (int mi = 0; mi < 2; ++mi) {
#pragma unroll
        for (int rh = 0; rh < 2; ++rh) {
            int p = m0 + wr + mi * 16 + (lane >> 2) + rh * 8;
            if (p >= PP) continue;
            float snp_p = g_snp[p], psum_p = g_psum[p];
            float4 pb = *(const float4*)(pboxes + 4 * p);
            float px0 = pb.x - 0.5f * pb.z, py0 = pb.y - 0.5f * pb.w;
            float px1 = pb.x + 0.5f * pb.z, py1 = pb.y + 0.5f * pb.w;
            float parea = pb.z * pb.w;
            const float* prow = g_prob + (size_t)p * NC;
#pragma unroll
            for (int ni = 0; ni < 4; ++ni) {
                int tl0 = wc + ni * 8 + 2 * (lane & 3);
                if (tl0 >= nvalid) continue;
                float r2[2];
#pragma unroll
                for (int cc = 0; cc < 2; ++cc) {
                    TInfo ti = sT[tl0 + cc];
                    float d1 = acc[0][mi][ni][rh * 2 + cc];
                    float d2 = acc[1][mi][ni][rh * 2 + cc];
                    float l1 = fabsf(pb.x - ti.cx) + fabsf(pb.y - ti.cy)
                             + fabsf(pb.z - ti.w) + fabsf(pb.w - ti.h);
                    float ix0 = fmaxf(px0, ti.x0), iy0 = fmaxf(py0, ti.y0);
                    float ix1 = fminf(px1, ti.x1), iy1 = fminf(py1, ti.y1);
                    float inter = fmaxf(ix1 - ix0, 0.f) * fmaxf(iy1 - iy0, 0.f);
                    float uni = parea + ti.area - inter;
                    float iou = inter / uni;
                    float ex0 = fminf(px0, ti.x0), ey0 = fminf(py0, ti.y0);
                    float ex1 = fmaxf(px1, ti.x1), ey1 = fmaxf(py1, ti.y1);
                    float enc = fmaxf(ex1 - ex0, 0.f) * fmaxf(ey1 - ey0, 0.f);
                    float giou = iou - (enc - uni) / enc;
                    float cmask = -(d1 + snp_p) * inv_hw;
                    float cdice = 1.f - (2.f * d2 + 1e-5f) / (psum_p + ti.tsum + 1e-5f);
                    float ccls = -prow[ti.lab];
                    r2[cc] = 5.f * l1 - 2.f * giou + 2.f * ccls + 5.f * cmask + 5.f * cdice;
                }
                *(float2*)(out + (size_t)p * TT + n0 + tl0) = make_float2(r2[0], r2[1]);
            }
        }
    }
}

// ---------------- launch ------------------------------------------------------
extern "C" void kernel_launch(void* const* d_in, const int* in_sizes, int n_in,
                              void* d_out, int out_size) {
    const float* pred_logits = (const float*)d_in[0];
    const float* pred_boxes  = (const float*)d_in[1];
    const float* pred_masks  = (const float*)d_in[2];
    const float* tgt_boxes   = (const float*)d_in[3];
    const float* tgt_masks   = (const float*)d_in[4];
    const void*  tgt_labels  = (const void*)d_in[5];
    float* out = (float*)d_out;

    aux_kernel<<<PP + TT + PP + 1, 256>>>(pred_logits, pred_masks, tgt_masks, tgt_labels);

    cudaFuncSetAttribute(gemm_kernel, cudaFuncAttributeMaxDynamicSharedMemorySize, SMEM_BYTES);
    gemm_kernel<<<dim3((TT + BN - 1) / BN, (PP + BM - 1) / BM), NTHREADS, SMEM_BYTES>>>(
        pred_boxes, tgt_boxes, out);
}

// round 11
// speedup vs baseline: 1.3618x; 1.2754x over previous
#include <cuda_runtime.h>
#include <cuda.h>
#include <cuda_bf16.h>
#include <cstdint>
#include <math.h>

// Problem dims (fixed by the dataset)
#define BSZ 16
#define QQ  300
#define NC  81
#define HH  64
#define WWD 64
#define TT  400
#define HM  128
#define PP  (BSZ*QQ)     // 4800
#define HWX (HH*WWD)     // 4096

// ---------------- scratch (device globals; no allocation allowed) -------------
__device__ __align__(1024) __nv_bfloat16 g_A1[(size_t)PP*HWX];   // logits bf16
__device__ __align__(1024) __nv_bfloat16 g_A2[(size_t)PP*HWX];   // sigmoid bf16
__device__ __align__(1024) __nv_bfloat16 g_tm[(size_t)TT*HWX];   // resized targets bf16
__device__ float g_tsum[TT];
__device__ float g_snp[PP];     // sum log_sigmoid(-m)
__device__ float g_psum[PP];    // sum sigmoid(m)
__device__ float g_prob[(size_t)PP*NC];
__device__ int   g_lab[TT];     // decoded labels

// ---------------- small helpers -----------------------------------------------
__device__ __forceinline__ float block_reduce_sum(float v, float* sh) {
    int lane = threadIdx.x & 31, w = threadIdx.x >> 5;
#pragma unroll
    for (int o = 16; o; o >>= 1) v += __shfl_down_sync(0xffffffffu, v, o);
    if (lane == 0) sh[w] = v;
    __syncthreads();
    if (w == 0) {
        v = (lane < 8) ? sh[lane] : 0.f;
#pragma unroll
        for (int o = 4; o; o >>= 1) v += __shfl_down_sync(0xffffffffu, v, o);
    }
    return v;  // valid on thread 0
}

__device__ __forceinline__ void taps64(int i, int& j0, float w[4]) {
    if (i == 0)       { j0 = 0;   w[0] = 3.f/7.f; w[1] = 3.f/7.f; w[2] = 1.f/7.f; w[3] = 0.f; }
    else if (i == 63) { j0 = 124; w[0] = 0.f;     w[1] = 1.f/7.f; w[2] = 3.f/7.f; w[3] = 3.f/7.f; }
    else              { j0 = 2*i - 1; w[0] = 0.125f; w[1] = 0.375f; w[2] = 0.375f; w[3] = 0.125f; }
}

__device__ __forceinline__ uint32_t smem_u32(const void* p) {
    uint32_t a;
    asm("{ .reg .u64 t; cvta.to.shared.u64 t, %1; cvt.u32.u64 %0, t; }" : "=r"(a) : "l"(p));
    return a;
}

#define SW128(off) ((off) ^ (((off) >> 3) & 0x70))

__device__ __forceinline__ void cpa16(void* dst, const void* src, bool v) {
    uint32_t d = (uint32_t)__cvta_generic_to_shared(dst);
    int n = v ? 16 : 0;
    asm volatile("cp.async.cg.shared.global [%0], [%1], 16, %2;\n" :: "r"(d), "l"(src), "r"(n));
}
__device__ __forceinline__ void cpcommit() { asm volatile("cp.async.commit_group;\n"); }

__device__ __forceinline__ void mma16816(float c[4], const uint32_t a[4], const uint32_t b[2]) {
    asm volatile(
        "mma.sync.aligned.m16n8k16.row.col.f32.bf16.bf16.f32 "
        "{%0,%1,%2,%3}, {%4,%5,%6,%7}, {%8,%9}, {%0,%1,%2,%3};\n"
        : "+f"(c[0]), "+f"(c[1]), "+f"(c[2]), "+f"(c[3])
        : "r"(a[0]), "r"(a[1]), "r"(a[2]), "r"(a[3]), "r"(b[0]), "r"(b[1]));
}

__device__ __forceinline__ void ldsm_x4(uint32_t r[4], uint32_t addr) {
    asm volatile("ldmatrix.sync.aligned.m8n8.x4.shared.b16 {%0,%1,%2,%3}, [%4];"
        : "=r"(r[0]), "=r"(r[1]), "=r"(r[2]), "=r"(r[3]) : "r"(addr));
}

#define MBARRIER_INIT(addr, cnt) \
    asm volatile("mbarrier.init.shared.b64 [%0], %1;" :: "r"((uint32_t)(addr)), "r"((uint32_t)(cnt)) : "memory")

#define MBARRIER_EXPECT_TX(addr, tx) \
    asm volatile("mbarrier.arrive.expect_tx.shared.b64 _, [%0], %1;" :: "r"((uint32_t)(addr)), "r"((uint32_t)(tx)) : "memory")

#define MBARRIER_WAIT_PARITY(mbar_smem_addr, phase_parity) do { \
    uint32_t _mbar = (uint32_t)(mbar_smem_addr); \
    uint32_t _parity = (uint32_t)(phase_parity); \
    uint32_t _done; \
    asm volatile( \
        "{\n\t.reg .pred p;\n\t" \
        "mbarrier.try_wait.parity.acquire.cta.shared::cta.b64 p, [%1], %2;\n\t" \
        "selp.b32 %0, 1, 0, p;\n\t}" \
        : "=r"(_done) : "r"(_mbar), "r"(_parity) : "memory"); \
    if (!_done) { \
        asm volatile( \
            "{\n\t.reg .pred P1;\n\t" \
            "WAIT_LOOP_%=:\n\t" \
            "mbarrier.try_wait.parity.acquire.cta.shared::cta.b64 P1, [%0], %1, 0x989680;\n\t" \
            "@P1 bra.uni WAIT_DONE_%=;\n\t" \
            "bra.uni WAIT_LOOP_%=;\n\t" \
            "WAIT_DONE_%=:\n\t}" \
            :: "r"(_mbar), "r"(_parity) : "memory"); \
    } \
} while (0)

__device__ __forceinline__ void tma2d(uint32_t dst, const CUtensorMap* tmap,
                                      int x, int y, uint32_t mbar) {
    asm volatile(
        "cp.async.bulk.tensor.2d.shared::cta.global.tile.mbarrier::complete_tx::bytes "
        "[%0], [%1, {%2, %3}], [%4];"
        :: "r"(dst), "l"(tmap), "r"(x), "r"(y), "r"(mbar) : "memory");
}

// ---------------- fused aux kernel (label + resize + prep + prob) -------------
__global__ void __launch_bounds__(256) aux_kernel(
    const float* __restrict__ logits, const float* __restrict__ masks,
    const float* __restrict__ tmasks, const void* __restrict__ labels) {
    __shared__ __align__(16) char smr[HM * HH * 4];   // 32KB, branch-dependent use
    int bid = blockIdx.x, tid = threadIdx.x;

    if (bid < PP) {
        int p = bid;
        const float4* src = (const float4*)(masks + (size_t)p * HWX);
        __nv_bfloat162* d1 = (__nv_bfloat162*)(g_A1 + (size_t)p * HWX);
        __nv_bfloat162* d2 = (__nv_bfloat162*)(g_A2 + (size_t)p * HWX);
        float accn = 0.f, accs = 0.f;
        for (int i = tid; i < HWX / 4; i += 256) {
            float4 v = src[i];
            float m[4] = {v.x, v.y, v.z, v.w};
            float s[4];
#pragma unroll
            for (int j = 0; j < 4; ++j) {
                float e = __expf(-fabsf(m[j]));
                float l = __logf(1.f + e);
                s[j] = (m[j] >= 0.f) ? __fdividef(1.f, 1.f + e)
                                     : __fdividef(e, 1.f + e);
                accn -= (fmaxf(m[j], 0.f) + l);
                accs += s[j];
            }
            __nv_bfloat162 a, b;
            a.x = __float2bfloat16(m[0]); a.y = __float2bfloat16(m[1]);
            b.x = __float2bfloat16(m[2]); b.y = __float2bfloat16(m[3]);
            d1[2*i] = a; d1[2*i + 1] = b;
            a.x = __float2bfloat16(s[0]); a.y = __float2bfloat16(s[1]);
            b.x = __float2bfloat16(s[2]); b.y = __float2bfloat16(s[3]);
            d2[2*i] = a; d2[2*i + 1] = b;
        }
        float* shred = (float*)smr;
        float tn = block_reduce_sum(accn, shred);
        __syncthreads();
        float ts = block_reduce_sum(accs, shred);
        if (tid == 0) { g_snp[p] = tn; g_psum[p] = ts; }
    } else if (bid < PP + TT) {
        int t = bid - PP;
        const float* src = tmasks + (size_t)t * HM * HM;
        float (*htmp)[HH] = (float(*)[HH])smr;
        for (int e = tid; e < HM * HH; e += 256) {
            int r = e >> 6, i = e & 63;
            int j0; float w[4]; taps64(i, j0, w);
            const float* row = src + r * HM;
            htmp[r][i] = w[0]*row[j0] + w[1]*row[j0+1] + w[2]*row[j0+2] + w[3]*row[j0+3];
        }
        __syncthreads();
        float lsum = 0.f;
        for (int e = tid; e < HWX; e += 256) {
            int o = e >> 6, i = e & 63;
            int j0; float w[4]; taps64(o, j0, w);
            float v = w[0]*htmp[j0][i] + w[1]*htmp[j0+1][i] + w[2]*htmp[j0+2][i] + w[3]*htmp[j0+3][i];
            g_tm[(size_t)t * HWX + e] = __float2bfloat16(v);
            lsum += v;
        }
        __syncthreads();
        __shared__ float shred2[8];
        float tot = block_reduce_sum(lsum, shred2);
        if (tid == 0) g_tsum[t] = tot;
    } else if (bid < PP + TT + PP) {
        int p = bid - PP - TT;
        float* sh = (float*)smr;
        float x = (tid < NC) ? logits[(size_t)p * NC + tid] : -1e30f;
        if (tid < 128) sh[tid] = x;
        __syncthreads();
        for (int s = 64; s > 0; s >>= 1) { if (tid < s) sh[tid] = fmaxf(sh[tid], sh[tid + s]); __syncthreads(); }
        float mx = sh[0]; __syncthreads();
        float e = (tid < NC) ? __expf(x - mx) : 0.f;
        if (tid < 128) sh[tid] = e;
        __syncthreads();
        for (int s = 64; s > 0; s >>= 1) { if (tid < s) sh[tid] += sh[tid + s]; __syncthreads(); }
        float inv = __fdividef(1.f, sh[0]);
        if (tid < NC) g_prob[(size_t)p * NC + tid] = e * inv;
    } else {
        __shared__ int odd_nz;
        if (tid == 0) odd_nz = 0;
        __syncthreads();
        const int* li = (const int*)labels;
        for (int i = tid; i < TT / 2; i += 256)
            if (li[2 * i + 1] != 0) atomicOr(&odd_nz, 1);
        __syncthreads();
        bool is64 = (odd_nz == 0);
        for (int t = tid; t < TT; t += 256)
            g_lab[t] = is64 ? (int)((const long long*)labels)[t] : li[t];
    }
}

// ---------------- shared epilogue pieces --------------------------------------
struct TInfo {
    float cx, cy, w, h, x0, y0, x1, y1, area, tsum;
    int lab, pad;
};

__device__ __forceinline__ void fill_tinfo(TInfo* sT, int n0, const float* tboxes, int tid) {
    if (tid < 128) {
        int t = n0 + tid;
        TInfo ti;
        if (t < TT) {
            float4 tb = *(const float4*)(tboxes + 4 * t);
            ti.cx = tb.x; ti.cy = tb.y; ti.w = tb.z; ti.h = tb.w;
            ti.x0 = tb.x - 0.5f * tb.z; ti.y0 = tb.y - 0.5f * tb.w;
            ti.x1 = tb.x + 0.5f * tb.z; ti.y1 = tb.y + 0.5f * tb.w;
            ti.area = tb.z * tb.w;
            ti.tsum = g_tsum[t];
            ti.lab = g_lab[t];
        } else {
            ti.cx = ti.cy = ti.w = ti.h = 0.f;
            ti.x0 = ti.y0 = ti.x1 = ti.y1 = 0.f;
            ti.area = ti.tsum = 0.f; ti.lab = 0;
        }
        ti.pad = 0;
        sT[tid] = ti;
    }
}

__device__ __forceinline__ void epilogue(
    const float acc[2][2][4][4], const TInfo* sT,
    const float* pboxes, float* out,
    int m0, int n0, int nvalid, int wr, int wc, int lane) {
    const float inv_hw = 1.0f / (float)HWX;
#pragma unroll
    for (int mi = 0; mi < 2; ++mi) {
#pragma unroll
        for (int rh = 0; rh < 2; ++rh) {
            int p = m0 + wr + mi * 16 + (lane >> 2) + rh * 8;
            if (p >= PP) continue;
            float snp_p = g_snp[p], psum_p = g_psum[p];
            float4 pb = *(const float4*)(pboxes + 4 * p);
            float px0 = pb.x - 0.5f * pb.z, py0 = pb.y - 0.5f * pb.w;
            float px1 = pb.x + 0.5f * pb.z, py1 = pb.y + 0.5f * pb.w;
            float parea = pb.z * pb.w;
            const float* prow = g_prob + (size_t)p * NC;
#pragma unroll
            for (int ni = 0; ni < 4; ++ni) {
                int tl0 = wc + ni * 8 + 2 * (lane & 3);
                if (tl0 >= nvalid) continue;
                float r2[2];
#pragma unroll
                for (int cc = 0; cc < 2; ++cc) {
                    TInfo ti = sT[tl0 + cc];
                    float d1 = acc[0][mi][ni][rh * 2 + cc];
                    float d2 = acc[1][mi][ni][rh * 2 + cc];
                    float l1 = fabsf(pb.x - ti.cx) + fabsf(pb.y - ti.cy)
                             + fabsf(pb.z - ti.w) + fabsf(pb.w - ti.h);
                    float ix0 = fmaxf(px0, ti.x0), iy0 = fmaxf(py0, ti.y0);
                    float ix1 = fminf(px1, ti.x1), iy1 = fminf(py1, ti.y1);
                    float inter = fmaxf(ix1 - ix0, 0.f) * fmaxf(iy1 - iy0, 0.f);
                    float uni = parea + ti.area - inter;
                    float iou = inter / uni;
                    float ex0 = fminf(px0, ti.x0), ey0 = fminf(py0, ti.y0);
                    float ex1 = fmaxf(px1, ti.x1), ey1 = fmaxf(py1, ti.y1);
                    float enc = fmaxf(ex1 - ex0, 0.f) * fmaxf(ey1 - ey0, 0.f);
                    float giou = iou - (enc - uni) / enc;
                    float cmask = -(d1 + snp_p) * inv_hw;
                    float cdice = 1.f - (2.f * d2 + 1e-5f) / (psum_p + ti.tsum + 1e-5f);
                    float ccls = -prow[ti.lab];
                    r2[cc] = 5.f * l1 - 2.f * giou + 2.f * ccls + 5.f * cmask + 5.f * cdice;
                }
                *(float2*)(out + (size_t)p * TT + n0 + tl0) = make_float2(r2[0], r2[1]);
            }
        }
    }
}

// ---------------- GEMM path A: TMA + mma.sync ---------------------------------
#define BM 128
#define BN 128
#define BKS 64                 // K elems per stage (128B rows -> SW128)
#define KTN (HWX / BKS)        // 64 stages
#define NSTG 4
#define MATB (128 * 128)       // 16KB per mat tile
#define STGB (3 * MATB)        // 48KB per stage
#define NTHREADS 512
#define DYN_SMEM (NSTG * STGB + 1024)

__global__ void __launch_bounds__(NTHREADS, 1) gemm_tma(
    const __grid_constant__ CUtensorMap tmA1,
    const __grid_constant__ CUtensorMap tmA2,
    const __grid_constant__ CUtensorMap tmB,
    const float* __restrict__ pboxes, const float* __restrict__ tboxes,
    float* __restrict__ out) {
    extern __shared__ char dsm[];
    __shared__ TInfo sT[128];
    __shared__ __align__(8) unsigned long long smbar[NSTG];

    uint32_t dbase = (smem_u32(dsm) + 1023) & ~1023u;
    uint32_t mb = smem_u32(smbar);

    int tid = threadIdx.x, lane = tid & 31, warp = tid >> 5;
    int n0 = blockIdx.x * BN, m0 = blockIdx.y * BM;
    int nvalid = min(BN, TT - n0);
    int wr = (warp & 3) * 32;
    int wc = (warp >> 2) * 32;

    if (tid == 0)
        for (int s = 0; s < NSTG; ++s) MBARRIER_INIT(mb + 8 * s, 1);
    fill_tinfo(sT, n0, tboxes, tid);
    __syncthreads();

    if (tid == 0) {
#pragma unroll
        for (int s = 0; s < 3; ++s) {
            uint32_t fb = mb + 8 * s;
            MBARRIER_EXPECT_TX(fb, STGB);
            uint32_t d = dbase + s * STGB;
            int x = s * BKS;
            tma2d(d,            &tmA1, x, m0, fb);
            tma2d(d + MATB,     &tmA2, x, m0, fb);
            tma2d(d + 2 * MATB, &tmB,  x, n0, fb);
        }
    }

    float acc[2][2][4][4];
#pragma unroll
    for (int a = 0; a < 2; ++a)
#pragma unroll
        for (int b = 0; b < 2; ++b)
#pragma unroll
            for (int c = 0; c < 4; ++c)
#pragma unroll
                for (int d = 0; d < 4; ++d) acc[a][b][c][d] = 0.f;

    int a_row_l = (lane & 15);
    int a_coff  = (lane >> 4) * 16;          // bytes
    int b_row_l = (lane & 7) + ((lane >> 4) * 8);
    int b_coff  = ((lane >> 3) & 1) * 16;    // bytes

    uint32_t phases = 0;

    for (int kt = 0; kt < KTN; ++kt) {
        __syncthreads();
        if (tid == 0 && kt + 3 < KTN) {
            int sl = (kt + 3) & 3;
            uint32_t fb = mb + 8 * sl;
            MBARRIER_EXPECT_TX(fb, STGB);
            uint32_t d = dbase + sl * STGB;
            int x = (kt + 3) * BKS;
            tma2d(d,            &tmA1, x, m0, fb);
            tma2d(d + MATB,     &tmA2, x, m0, fb);
            tma2d(d + 2 * MATB, &tmB,  x, n0, fb);
        }
        int sl = kt & 3;
        MBARRIER_WAIT_PARITY(mb + 8 * sl, (phases >> sl) & 1);
        phases ^= 1u << sl;

        uint32_t sb = dbase + sl * STGB;
#pragma unroll
        for (int ks = 0; ks < 4; ++ks) {
            int cbyte = ks * 32;
            uint32_t af[2][2][4];
#pragma unroll
            for (int mi = 0; mi < 2; ++mi) {
                uint32_t off = (uint32_t)((wr + mi * 16 + a_row_l) * 128 + cbyte + a_coff);
                uint32_t sw = SW128(off);
                ldsm_x4(af[0][mi], sb + sw);
                ldsm_x4(af[1][mi], sb + MATB + sw);
            }
            uint32_t bf[4][2];
#pragma unroll
            for (int nh = 0; nh < 2; ++nh) {
                uint32_t regs[4];
                uint32_t off = (uint32_t)((wc + nh * 16 + b_row_l) * 128 + cbyte + b_coff);
                ldsm_x4(regs, sb + 2 * MATB + SW128(off));
                bf[nh * 2][0] = regs[0]; bf[nh * 2][1] = regs[1];
                bf[nh * 2 + 1][0] = regs[2]; bf[nh * 2 + 1][1] = regs[3];
            }
#pragma unroll
            for (int s2 = 0; s2 < 2; ++s2)
#pragma unroll
                for (int mi = 0; mi < 2; ++mi)
#pragma unroll
                    for (int ni = 0; ni < 4; ++ni)
                        mma16816(acc[s2][mi][ni], af[s2][mi], bf[ni]);
        }
    }

    epilogue(acc, sT, pboxes, out, m0, n0, nvalid, wr, wc, lane);
}

// ---------------- GEMM path B: cp.async fallback (round-9, proven) ------------
#define BK 32
#define SAK 40
#define STAGES 4
#define KT_N (HWX / BK)
#define STAGE_ELEMS (3 * BM * SAK)
#define SMEM_BYTES_FB (STAGES * STAGE_ELEMS * 2 + 128 * (int)sizeof(TInfo))

__global__ void __launch_bounds__(NTHREADS, 1) gemm_cpasync(
    const float* __restrict__ pboxes, const float* __restrict__ tboxes,
    float* __restrict__ out) {
    extern __shared__ __align__(16) char smem_raw[];
    __nv_bfloat16* sBuf = (__nv_bfloat16*)smem_raw;
    TInfo* sT = (TInfo*)(smem_raw + STAGES * STAGE_ELEMS * 2);

    int tid = threadIdx.x, lane = tid & 31, warp = tid >> 5;
    int n0 = blockIdx.x * BN, m0 = blockIdx.y * BM;
    int nvalid = min(BN, TT - n0);
    int wr = (warp & 3) * 32;
    int wc = (warp >> 2) * 32;

    fill_tinfo(sT, n0, tboxes, tid);

    float acc[2][2][4][4];
#pragma unroll
    for (int a = 0; a < 2; ++a)
#pragma unroll
        for (int b = 0; b < 2; ++b)
#pragma unroll
            for (int c = 0; c < 4; ++c)
#pragma unroll
                for (int d = 0; d < 4; ++d) acc[a][b][c][d] = 0.f;

    int a_row_l = (lane & 15);
    int a_col_l = (lane >> 4) * 8;
    int b_row_l = (lane & 7) + ((lane >> 4) * 8);
    int b_col_l = ((lane >> 3) & 1) * 8;

    auto loadStage = [&](int slot, int kt) {
        __nv_bfloat16* base = sBuf + slot * STAGE_ELEMS;
        int k0 = kt * BK;
#pragma unroll
        for (int it = 0; it < 3; ++it) {
            int i = tid + it * NTHREADS;
            int mat = i >> 9;
            int rem = i & 511;
            int row = rem >> 2;
            int ch  = rem & 3;
            __nv_bfloat16* dst = base + mat * BM * SAK + row * SAK + ch * 8;
            const __nv_bfloat16* src;
            bool v;
            if (mat < 2) {
                int p = m0 + row;
                v = p < PP;
                const __nv_bfloat16* g = (mat == 0) ? g_A1 : g_A2;
                src = g + ((size_t)(v ? p : 0) * HWX + k0 + ch * 8);
            } else {
                int t = n0 + row;
                v = t < TT;
                src = g_tm + ((size_t)(v ? t : 0) * HWX + k0 + ch * 8);
            }
            cpa16(dst, src, v);
        }
        cpcommit();
    };

    loadStage(0, 0);
    loadStage(1, 1);
    loadStage(2, 2);

    for (int kt = 0; kt < KT_N; ++kt) {
        asm volatile("cp.async.wait_group 2;" ::: "memory");
        __syncthreads();
        int kl = kt + STAGES - 1;
        if (kl < KT_N) loadStage(kl & 3, kl);

        const __nv_bfloat16* S = sBuf + (kt & 3) * STAGE_ELEMS;
        uint32_t sbA1 = (uint32_t)__cvta_generic_to_shared(S);
        uint32_t sbA2 = sbA1 + BM * SAK * 2;
        uint32_t sbB  = sbA1 + 2 * BM * SAK * 2;
#pragma unroll
        for (int ks = 0; ks < 2; ++ks) {
            int cb = ks * 16;
            uint32_t af[2][2][4];
#pragma unroll
            for (int mi = 0; mi < 2; ++mi) {
                uint32_t ra = ((wr + mi * 16 + a_row_l) * SAK + cb + a_col_l) * 2;
                ldsm_x4(af[0][mi], sbA1 + ra);
                ldsm_x4(af[1][mi], sbA2 + ra);
            }
            uint32_t bf[4][2];
#pragma unroll
            for (int nh = 0; nh < 2; ++nh) {
                uint32_t regs[4];
                uint32_t rb = ((wc + nh * 16 + b_row_l) * SAK + cb + b_col_l) * 2;
                ldsm_x4(regs, sbB + rb);
                bf[nh * 2][0] = regs[0]; bf[nh * 2][1] = regs[1];
                bf[nh * 2 + 1][0] = regs[2]; bf[nh * 2 + 1][1] = regs[3];
            }
#pragma unroll
            for (int s2 = 0; s2 < 2; ++s2)
#pragma unroll
                for (int mi = 0; mi < 2; ++mi)
#pragma unroll
                    for (int ni = 0; ni < 4; ++ni)
                        mma16816(acc[s2][mi][ni], af[s2][mi], bf[ni]);
        }
    }

    epilogue(acc, sT, pboxes, out, m0, n0, nvalid, wr, wc, lane);
}

// ---------------- host: tensormap encoding + launch ---------------------------
typedef CUresult (*PFN_encodeTiled)(
    CUtensorMap*, CUtensorMapDataType, cuuint32_t, void*,
    const cuuint64_t*, const cuuint64_t*, const cuuint32_t*, const cuuint32_t*,
    CUtensorMapInterleave, CUtensorMapSwizzle, CUtensorMapL2promotion,
    CUtensorMapFloatOOBfill);

static CUresult encode_map(PFN_encodeTiled enc, CUtensorMap* tm, void* ptr,
                           unsigned long long rows) {
    cuuint64_t dims[2]    = {(cuuint64_t)HWX, (cuuint64_t)rows};
    cuuint64_t strides[1] = {(cuuint64_t)HWX * 2};
    cuuint32_t box[2]     = {BKS, 128};
    cuuint32_t estr[2]    = {1, 1};
    return enc(tm, CU_TENSOR_MAP_DATA_TYPE_BFLOAT16, 2, ptr, dims, strides, box, estr,
               CU_TENSOR_MAP_INTERLEAVE_NONE, CU_TENSOR_MAP_SWIZZLE_128B,
               CU_TENSOR_MAP_L2_PROMOTION_L2_128B, CU_TENSOR_MAP_FLOAT_OOB_FILL_NONE);
}

extern "C" void kernel_launch(void* const* d_in, const int* in_sizes, int n_in,
                              void* d_out, int out_size) {
    const float* pred_logits = (const float*)d_in[0];
    const float* pred_boxes  = (const float*)d_in[1];
    const float* pred_masks  = (const float*)d_in[2];
    const float* tgt_boxes   = (const float*)d_in[3];
    const float* tgt_masks   = (const float*)d_in[4];
    const void*  tgt_labels  = (const void*)d_in[5];
    float* out = (float*)d_out;

    aux_kernel<<<PP + TT + PP + 1, 256>>>(pred_logits, pred_masks, tgt_masks, tgt_labels);

    // Try the TMA path; verified fallback to the proven cp.async path.
    bool tma_ok = false;
    alignas(64) CUtensorMap tmA1, tmA2, tmB;
    void* fp = nullptr;
#if CUDART_VERSION >= 12000
    cudaDriverEntryPointQueryResult qr;
    cudaError_t e0 = cudaGetDriverEntryPoint("cuTensorMapEncodeTiled", &fp,
                                             cudaEnableDefault, &qr);
#else
    cudaError_t e0 = cudaGetDriverEntryPoint("cuTensorMapEncodeTiled", &fp,
                                             cudaEnableDefault);
#endif
    if (e0 == cudaSuccess && fp != nullptr) {
        PFN_encodeTiled enc = (PFN_encodeTiled)fp;
        void *pa1 = nullptr, *pa2 = nullptr, *pb = nullptr;
        cudaError_t s1 = cudaGetSymbolAddress(&pa1, g_A1);
        cudaError_t s2 = cudaGetSymbolAddress(&pa2, g_A2);
        cudaError_t s3 = cudaGetSymbolAddress(&pb,  g_tm);
        if (s1 == cudaSuccess && s2 == cudaSuccess && s3 == cudaSuccess) {
            CUresult r1 = encode_map(enc, &tmA1, pa1, PP);
            CUresult r2 = encode_map(enc, &tmA2, pa2, PP);
            CUresult r3 = encode_map(enc, &tmB,  pb,  TT);
            tma_ok = (r1 == CUDA_SUCCESS && r2 == CUDA_SUCCESS && r3 == CUDA_SUCCESS);
        }
    }

    dim3 grid((TT + BN - 1) / BN, (PP + BM - 1) / BM);
    if (tma_ok) {
        cudaFuncSetAttribute(gemm_tma, cudaFuncAttributeMaxDynamicSharedMemorySize, DYN_SMEM);
        gemm_tma<<<grid, NTHREADS, DYN_SMEM>>>(tmA1, tmA2, tmB, pred_boxes, tgt_boxes, out);
    } else {
        cudaFuncSetAttribute(gemm_cpasync, cudaFuncAttributeMaxDynamicSharedMemorySize, SMEM_BYTES_FB);
        gemm_cpasync<<<grid, NTHREADS, SMEM_BYTES_FB>>>(pred_boxes, tgt_boxes, out);
    }
}